// round 8
// baseline (speedup 1.0000x reference)
#include <cuda_runtime.h>
#include <cstdint>
#include <math.h>

// Problem constants
#define BB   4
#define SS_  1024
#define DD   1024
#define HH_  16
#define DK_  64
#define DFF_ 4096
#define TOK  (BB*SS_)          // 4096 tokens

// ---------------------------------------------------------------------------
// Scratch (static __device__ arrays — the sanctioned no-alloc mechanism)
// ---------------------------------------------------------------------------
__device__ float g_nx  [TOK*DD];
__device__ float g_q   [TOK*DD];
__device__ float g_k   [TOK*DD];
__device__ float g_v   [TOK*DD];
__device__ float g_ctx [TOK*DD];
__device__ float g_x1  [TOK*DD];
__device__ float g_nx2r[TOK*DD];
__device__ float g_nx2e[TOK*DD];
__device__ float g_ff  [TOK*DFF_];
__device__ float g_y   [TOK*DD];
__device__ float g_lny [TOK*DD];
// transposed weights (k-major rows: wT[n][k] = w[k][n])
__device__ float g_wqT [DD*DD];
__device__ float g_wkT [DD*DD];
__device__ float g_wvT [DD*DD];
__device__ float g_woT [DD*DD];
__device__ float g_w1T [DFF_*DD];
__device__ float g_w2T [DD*DFF_];
__device__ float g_w3T [DD*DD];

#define DEVI __device__ __forceinline__

DEVI float f2tf32(float x) {
    uint32_t u;
    asm("cvt.rna.tf32.f32 %0, %1;" : "=r"(u) : "f"(x));
    return __uint_as_float(u);
}
DEVI float gelu_exact(float x) {
    return 0.5f * x * (1.0f + erff(x * 0.70710678118654752f));
}
DEVI void cp_async16(uint32_t dst, const void* src, bool pred) {
    int sz = pred ? 16 : 0;
    asm volatile("cp.async.cg.shared.global [%0], [%1], 16, %2;\n"
                 :: "r"(dst), "l"(src), "r"(sz));
}
DEVI void cp_commit() { asm volatile("cp.async.commit_group;\n"); }
DEVI void cp_wait1()  { asm volatile("cp.async.wait_group 1;\n"); }
DEVI void cp_wait2()  { asm volatile("cp.async.wait_group 2;\n"); }

DEVI void mma_tf32(float (&c)[4], float a0, float a1, float a2, float a3,
                   float b0, float b1) {
    asm volatile(
        "mma.sync.aligned.m16n8k8.row.col.f32.tf32.tf32.f32 "
        "{%0,%1,%2,%3}, {%4,%5,%6,%7}, {%8,%9}, {%0,%1,%2,%3};"
        : "+f"(c[0]), "+f"(c[1]), "+f"(c[2]), "+f"(c[3])
        : "r"(__float_as_uint(a0)), "r"(__float_as_uint(a1)),
          "r"(__float_as_uint(a2)), "r"(__float_as_uint(a3)),
          "r"(__float_as_uint(b0)), "r"(__float_as_uint(b1)));
}

enum { EPI_NONE = 0, EPI_BIAS = 1, EPI_BIAS_GELU = 2, EPI_BIAS_RES = 3,
       EPI_BIAS_RES2 = 4 };

// ---------------------------------------------------------------------------
// Tiled 32x32 transpose: out[C][R] = in[R][C]^T. Dims multiples of 32.
// Grid (C/32, R/32), block (32, 8).
// ---------------------------------------------------------------------------
__global__ void transpose_kernel(const float* __restrict__ in, float* __restrict__ out,
                                 int R, int C)
{
    __shared__ float tile[32][33];
    const int tx = threadIdx.x, ty = threadIdx.y;
    const int r0 = blockIdx.y * 32, c0 = blockIdx.x * 32;
#pragma unroll
    for (int i = 0; i < 32; i += 8)
        tile[ty + i][tx] = in[(size_t)(r0 + ty + i) * C + c0 + tx];
    __syncthreads();
#pragma unroll
    for (int i = 0; i < 32; i += 8)
        out[(size_t)(c0 + ty + i) * R + r0 + tx] = tile[tx][ty + i];
}

// ---------------------------------------------------------------------------
// Pipelined tf32 GEMM, tile 128x128x32, 256 threads, warp tile 64x32.
// 3-stage cp.async pipeline. A activations pre-rounded tf32 rows [M][K];
// BT = transposed weights [N][K] (raw fp32, mma truncates).
// k-slot permutation: mma hw k-slot (cq, cq+4) <-> physical (2cq, 2cq+1),
// so BOTH A and B fragments are contiguous float2 -> LDS.64.
// SMEM floats: A[3][4][128][8] @0 (3*4096), B[3][128][40] @12288 (3*5120).
// Total 27648 floats = 110592 bytes.
// ---------------------------------------------------------------------------
#define GEMM_SMEM 110592

template <int EPI, bool ROUND>
__global__ __launch_bounds__(256, 2)
void gemm_tf32_kernel(const float* __restrict__ A, int lda,
                      const float* __restrict__ BT, int ldbt,
                      float* __restrict__ C, int ldc,
                      int M, int N, int K,
                      const float* __restrict__ bias,
                      const float* __restrict__ res1,
                      const float* __restrict__ res2)
{
    extern __shared__ float smem[];
    const uint32_t smem_u = (uint32_t)__cvta_generic_to_shared(smem);

    const int tid  = threadIdx.x;
    const int warp = tid >> 5;
    const int lane = tid & 31;
    const int wm = (warp >> 2) * 64;
    const int wn = (warp & 3) * 32;
    const int r  = lane >> 2;
    const int cq = lane & 3;

    const int blockM = blockIdx.y * 128;
    const int blockN = blockIdx.x * 128;

    float acc[4][4][4];
#pragma unroll
    for (int mt = 0; mt < 4; mt++)
#pragma unroll
        for (int nt = 0; nt < 4; nt++)
#pragma unroll
            for (int i = 0; i < 4; i++) acc[mt][nt][i] = 0.0f;

    // stage k-tile t into pipeline slot s
    auto stage = [&](int t, int s) {
        const int k0 = t << 5;
        const uint32_t abase = smem_u + (uint32_t)(s * 4096) * 4u;
#pragma unroll
        for (int i = 0; i < 4; i++) {
            int idx = tid + i * 256;
            int row = idx >> 3;
            int c4  = (idx & 7) * 4;
            int gr  = blockM + row;
            bool ok = (gr < M);
            const float* src = A + (ok ? ((size_t)gr * lda + (k0 + c4)) : 0);
            uint32_t dst = abase + (uint32_t)((((c4 >> 3) * 128 + row) * 8 + (c4 & 7)) * 4);
            cp_async16(dst, src, ok);
        }
        const uint32_t bbase = smem_u + (uint32_t)((12288 + s * 5120) * 4);
#pragma unroll
        for (int i = 0; i < 2; i++) {
            int idx = tid + i * 256;          // 512 quarters: 128 n x 8
            int n   = idx >> 2;               // 0..127
            int k4  = (idx & 3) * 8;          // 0,8,16,24  (two 16B per thread)
            int gn  = blockN + n;
            bool ok = (gn < N);
            const float* src = BT + (ok ? ((size_t)gn * ldbt + (k0 + k4)) : 0);
            uint32_t dst = bbase + (uint32_t)((n * 40 + k4) * 4);
            cp_async16(dst,      src,     ok);
            cp_async16(dst + 16, src + 4, ok);
        }
    };

    const int T = K >> 5;
    stage(0, 0);
    cp_commit();
    if (T > 1) stage(1, 1);
    cp_commit();

    int slot = 0;
    for (int t = 0; t < T; t++) {
        if (t + 2 < T) stage(t + 2, (slot + 2) % 3);
        cp_commit();
        cp_wait2();
        __syncthreads();

        const float* Ab = smem + slot * 4096;
        const float* Bb = smem + 12288 + slot * 5120;
#pragma unroll
        for (int kkg = 0; kkg < 4; kkg++) {
            float2 av[4][2];
#pragma unroll
            for (int mt = 0; mt < 4; mt++) {
                int row = wm + mt * 16 + r;
                av[mt][0] = *(const float2*)(Ab + (kkg * 128 + row    ) * 8 + 2 * cq);
                av[mt][1] = *(const float2*)(Ab + (kkg * 128 + row + 8) * 8 + 2 * cq);
            }
            float2 bv[4];
#pragma unroll
            for (int nt = 0; nt < 4; nt++)
                bv[nt] = *(const float2*)(Bb + (wn + nt * 8 + r) * 40 + kkg * 8 + 2 * cq);
#pragma unroll
            for (int nt = 0; nt < 4; nt++)
#pragma unroll
                for (int mt = 0; mt < 4; mt++)
                    mma_tf32(acc[mt][nt], av[mt][0].x, av[mt][1].x,
                             av[mt][0].y, av[mt][1].y, bv[nt].x, bv[nt].y);
        }
        __syncthreads();
        slot = (slot + 1) % 3;
    }

    // ---- epilogue + store ----
#pragma unroll
    for (int mt = 0; mt < 4; mt++) {
#pragma unroll
        for (int nt = 0; nt < 4; nt++) {
#pragma unroll
            for (int rh = 0; rh < 2; rh++) {
                int grow = blockM + wm + mt * 16 + r + rh * 8;
                int gcol = blockN + wn + nt * 8 + cq * 2;
                if (grow < M && gcol < N) {
                    float v0 = acc[mt][nt][rh * 2 + 0];
                    float v1 = acc[mt][nt][rh * 2 + 1];
                    size_t cidx = (size_t)grow * ldc + gcol;
                    if (EPI != EPI_NONE) {
                        v0 += bias[gcol];
                        v1 += bias[gcol + 1];
                    }
                    if (EPI == EPI_BIAS_GELU) { v0 = gelu_exact(v0); v1 = gelu_exact(v1); }
                    if (EPI == EPI_BIAS_RES || EPI == EPI_BIAS_RES2) {
                        v0 += res1[cidx]; v1 += res1[cidx + 1];
                    }
                    if (EPI == EPI_BIAS_RES2) {
                        v0 += res2[cidx]; v1 += res2[cidx + 1];
                    }
                    if (ROUND) { v0 = f2tf32(v0); v1 = f2tf32(v1); }
                    *(float2*)(C + cidx) = make_float2(v0, v1);
                }
            }
        }
    }
}

// ---------------------------------------------------------------------------
// Fused flash attention (unchanged from R7 winner).
// ---------------------------------------------------------------------------
#define FA_SMEM 107008

__global__ __launch_bounds__(256, 1)
void flash_attn_kernel(const float* __restrict__ Q, const float* __restrict__ K,
                       const float* __restrict__ V, const float* __restrict__ relt,
                       float* __restrict__ ctx)
{
    extern __shared__ float sm[];
    const uint32_t sm_u = (uint32_t)__cvta_generic_to_shared(sm);

    const int tid  = threadIdx.x;
    const int warp = tid >> 5;
    const int lane = tid & 31;
    const int r  = lane >> 2;
    const int cq = lane & 3;
    const int qt = blockIdx.x;
    const int bh = blockIdx.y;
    const int b  = bh >> 4, h = bh & 15;

    const size_t base = (size_t)b * SS_ * DD + (size_t)h * DK_;
    const int qrow = qt * 128 + warp * 16 + r;

    if (tid < 127) sm[26624 + tid] = relt[tid * HH_ + h];

    const float* qp  = Q + base + (size_t)qrow * DD;
    const float* qp8 = qp + (size_t)8 * DD;
    float2 qa[8][2];
#pragma unroll
    for (int kk = 0; kk < 8; kk++) {
        float2 v0 = *(const float2*)(qp  + kk * 8 + 2 * cq);
        float2 v1 = *(const float2*)(qp8 + kk * 8 + 2 * cq);
        qa[kk][0] = make_float2(v0.x * 0.125f, v0.y * 0.125f);
        qa[kk][1] = make_float2(v1.x * 0.125f, v1.y * 0.125f);
    }

    auto stage = [&](int j, int bsel) {
#pragma unroll
        for (int i = 0; i < 4; i++) {
            int idx = tid + i * 256;
            int t   = idx >> 4;
            int sg  = (idx & 15) * 4;
            const float* kr_ = K + base + (size_t)(j * 64 + t) * DD + sg;
            const float* vr_ = V + base + (size_t)(j * 64 + t) * DD + sg;
            cp_async16(sm_u + (uint32_t)((bsel * 4352 + t * 68 + sg) * 4), kr_, true);
            cp_async16(sm_u + (uint32_t)(((8704 + bsel * 4352) + t * 68 + sg) * 4), vr_, true);
        }
    };

    float oacc[8][4];
#pragma unroll
    for (int nf = 0; nf < 8; nf++)
#pragma unroll
        for (int i = 0; i < 4; i++) oacc[nf][i] = 0.0f;
    float m0 = -3e38f, m1 = -3e38f, l0 = 0.0f, l1 = 0.0f;

    stage(0, 0);
    cp_commit();

    float* Pw = sm + 17408 + warp * 1152;
    const float* bias_sm = sm + 26624;

    for (int j = 0; j < 16; j++) {
        const int cur = j & 1;
        if (j + 1 < 16) stage(j + 1, cur ^ 1);
        cp_commit();
        cp_wait1();
        __syncthreads();

        const float* Ks = sm + cur * 4352;
        const float* Vs = sm + 8704 + cur * 4352;

        float s[8][4];
#pragma unroll
        for (int nf = 0; nf < 8; nf++)
            s[nf][0] = s[nf][1] = s[nf][2] = s[nf][3] = 0.0f;
#pragma unroll
        for (int kk = 0; kk < 8; kk++) {
#pragma unroll
            for (int nf = 0; nf < 8; nf++) {
                float2 kb = *(const float2*)(Ks + (nf * 8 + r) * 68 + kk * 8 + 2 * cq);
                mma_tf32(s[nf], qa[kk][0].x, qa[kk][1].x, qa[kk][0].y, qa[kk][1].y,
                         kb.x, kb.y);
            }
        }

        const int row0 = qrow, row1 = qrow + 8;
        const int colb = j * 64 + 2 * cq;
#pragma unroll
        for (int nf = 0; nf < 8; nf++) {
            int c0 = colb + nf * 8, c1 = c0 + 1;
            int d00 = min(max(c0 - row0 + 63, 0), 126);
            int d01 = min(max(c1 - row0 + 63, 0), 126);
            int d10 = min(max(c0 - row1 + 63, 0), 126);
            int d11 = min(max(c1 - row1 + 63, 0), 126);
            s[nf][0] += bias_sm[d00];
            s[nf][1] += bias_sm[d01];
            s[nf][2] += bias_sm[d10];
            s[nf][3] += bias_sm[d11];
        }

        float rm0 = -3e38f, rm1 = -3e38f;
#pragma unroll
        for (int nf = 0; nf < 8; nf++) {
            rm0 = fmaxf(rm0, fmaxf(s[nf][0], s[nf][1]));
            rm1 = fmaxf(rm1, fmaxf(s[nf][2], s[nf][3]));
        }
        rm0 = fmaxf(rm0, __shfl_xor_sync(0xffffffffu, rm0, 1));
        rm0 = fmaxf(rm0, __shfl_xor_sync(0xffffffffu, rm0, 2));
        rm1 = fmaxf(rm1, __shfl_xor_sync(0xffffffffu, rm1, 1));
        rm1 = fmaxf(rm1, __shfl_xor_sync(0xffffffffu, rm1, 2));
        float mn0 = fmaxf(m0, rm0), mn1 = fmaxf(m1, rm1);
        float a0 = __expf(m0 - mn0), a1 = __expf(m1 - mn1);
        m0 = mn0; m1 = mn1;
        float sum0 = 0.0f, sum1 = 0.0f;
#pragma unroll
        for (int nf = 0; nf < 8; nf++) {
            s[nf][0] = __expf(s[nf][0] - mn0);
            s[nf][1] = __expf(s[nf][1] - mn0);
            s[nf][2] = __expf(s[nf][2] - mn1);
            s[nf][3] = __expf(s[nf][3] - mn1);
            sum0 += s[nf][0] + s[nf][1];
            sum1 += s[nf][2] + s[nf][3];
        }
        sum0 += __shfl_xor_sync(0xffffffffu, sum0, 1);
        sum0 += __shfl_xor_sync(0xffffffffu, sum0, 2);
        sum1 += __shfl_xor_sync(0xffffffffu, sum1, 1);
        sum1 += __shfl_xor_sync(0xffffffffu, sum1, 2);
        l0 = l0 * a0 + sum0;
        l1 = l1 * a1 + sum1;
#pragma unroll
        for (int nf = 0; nf < 8; nf++) {
            oacc[nf][0] *= a0; oacc[nf][1] *= a0;
            oacc[nf][2] *= a1; oacc[nf][3] *= a1;
        }

#pragma unroll
        for (int nf = 0; nf < 8; nf++) {
            *(float2*)(Pw + r * 72 + nf * 8 + 2 * cq) =
                make_float2(f2tf32(s[nf][0]), f2tf32(s[nf][1]));
            *(float2*)(Pw + (r + 8) * 72 + nf * 8 + 2 * cq) =
                make_float2(f2tf32(s[nf][2]), f2tf32(s[nf][3]));
        }
        __syncwarp();

#pragma unroll
        for (int kk = 0; kk < 8; kk++) {
            float2 pa0 = *(const float2*)(Pw + r * 72 + kk * 8 + 2 * cq);
            float2 pa1 = *(const float2*)(Pw + (r + 8) * 72 + kk * 8 + 2 * cq);
#pragma unroll
            for (int nf = 0; nf < 8; nf++) {
                float vb0 = Vs[(kk * 8 + 2 * cq    ) * 68 + nf * 8 + r];
                float vb1 = Vs[(kk * 8 + 2 * cq + 1) * 68 + nf * 8 + r];
                mma_tf32(oacc[nf], pa0.x, pa1.x, pa0.y, pa1.y, vb0, vb1);
            }
        }
        __syncthreads();
    }

    const float inv0 = 1.0f / l0, inv1 = 1.0f / l1;
    float* op  = ctx + base + (size_t)qrow * DD;
    float* op8 = op + (size_t)8 * DD;
#pragma unroll
    for (int nf = 0; nf < 8; nf++) {
        *(float2*)(op + nf * 8 + 2 * cq) =
            make_float2(f2tf32(oacc[nf][0] * inv0), f2tf32(oacc[nf][1] * inv0));
        *(float2*)(op8 + nf * 8 + 2 * cq) =
            make_float2(f2tf32(oacc[nf][2] * inv1), f2tf32(oacc[nf][3] * inv1));
    }
}

// ---------------------------------------------------------------------------
// LayerNorm (unchanged)
// ---------------------------------------------------------------------------
template <bool DUAL>
__global__ void ln_kernel(const float* __restrict__ x, const float* __restrict__ g,
                          const float* __restrict__ b,
                          float* __restrict__ out_r, float* __restrict__ out_e)
{
    __shared__ float sb[8];
    const int row = blockIdx.x;
    const int t   = threadIdx.x;
    float4 v = ((const float4*)(x + (size_t)row * DD))[t];

    float s = v.x + v.y + v.z + v.w;
#pragma unroll
    for (int o = 16; o; o >>= 1) s += __shfl_xor_sync(0xffffffffu, s, o);
    if ((t & 31) == 0) sb[t >> 5] = s;
    __syncthreads();
    float mean = (sb[0]+sb[1]+sb[2]+sb[3]+sb[4]+sb[5]+sb[6]+sb[7]) * (1.0f / DD);
    __syncthreads();

    float d0 = v.x - mean, d1 = v.y - mean, d2 = v.z - mean, d3 = v.w - mean;
    float s2 = d0*d0 + d1*d1 + d2*d2 + d3*d3;
#pragma unroll
    for (int o = 16; o; o >>= 1) s2 += __shfl_xor_sync(0xffffffffu, s2, o);
    if ((t & 31) == 0) sb[t >> 5] = s2;
    __syncthreads();
    float var = (sb[0]+sb[1]+sb[2]+sb[3]+sb[4]+sb[5]+sb[6]+sb[7]) * (1.0f / DD);
    float inv = rsqrtf(var + 1e-5f);

    float4 gv = ((const float4*)g)[t];
    float4 bv = ((const float4*)b)[t];
    float4 o4 = make_float4(d0 * inv * gv.x + bv.x, d1 * inv * gv.y + bv.y,
                            d2 * inv * gv.z + bv.z, d3 * inv * gv.w + bv.w);
    if (DUAL)
        ((float4*)(out_e + (size_t)row * DD))[t] = o4;
    ((float4*)(out_r + (size_t)row * DD))[t] =
        make_float4(f2tf32(o4.x), f2tf32(o4.y), f2tf32(o4.z), f2tf32(o4.w));
}

// ---------------------------------------------------------------------------
// Launch
// ---------------------------------------------------------------------------
extern "C" void kernel_launch(void* const* d_in, const int* in_sizes, int n_in,
                              void* d_out, int out_size)
{
    (void)in_sizes; (void)n_in; (void)out_size;
    const float* x    = (const float*)d_in[0];
    const float* wq   = (const float*)d_in[1];
    const float* bq   = (const float*)d_in[2];
    const float* wk   = (const float*)d_in[3];
    const float* bk   = (const float*)d_in[4];
    const float* wv   = (const float*)d_in[5];
    const float* bv   = (const float*)d_in[6];
    const float* wo   = (const float*)d_in[7];
    const float* bo   = (const float*)d_in[8];
    const float* relt = (const float*)d_in[9];
    const float* g1   = (const float*)d_in[10];
    const float* be1  = (const float*)d_in[11];
    const float* g2   = (const float*)d_in[12];
    const float* be2  = (const float*)d_in[13];
    const float* w1   = (const float*)d_in[14];
    const float* b1   = (const float*)d_in[15];
    const float* w2   = (const float*)d_in[16];
    const float* b2   = (const float*)d_in[17];
    const float* w3   = (const float*)d_in[18];
    const float* b3   = (const float*)d_in[19];
    const float* gf   = (const float*)d_in[20];
    const float* bf   = (const float*)d_in[21];
    float* out = (float*)d_out;

    float *nx, *q, *k, *v, *ctx, *x1, *nx2r, *nx2e, *ff, *y, *lny;
    float *wqT, *wkT, *wvT, *woT, *w1T, *w2T, *w3T;
    cudaGetSymbolAddress((void**)&nx,   g_nx);
    cudaGetSymbolAddress((void**)&q,    g_q);
    cudaGetSymbolAddress((void**)&k,    g_k);
    cudaGetSymbolAddress((void**)&v,    g_v);
    cudaGetSymbolAddress((void**)&ctx,  g_ctx);
    cudaGetSymbolAddress((void**)&x1,   g_x1);
    cudaGetSymbolAddress((void**)&nx2r, g_nx2r);
    cudaGetSymbolAddress((void**)&nx2e, g_nx2e);
    cudaGetSymbolAddress((void**)&ff,   g_ff);
    cudaGetSymbolAddress((void**)&y,    g_y);
    cudaGetSymbolAddress((void**)&lny,  g_lny);
    cudaGetSymbolAddress((void**)&wqT,  g_wqT);
    cudaGetSymbolAddress((void**)&wkT,  g_wkT);
    cudaGetSymbolAddress((void**)&wvT,  g_wvT);
    cudaGetSymbolAddress((void**)&woT,  g_woT);
    cudaGetSymbolAddress((void**)&w1T,  g_w1T);
    cudaGetSymbolAddress((void**)&w2T,  g_w2T);
    cudaGetSymbolAddress((void**)&w3T,  g_w3T);

    cudaFuncSetAttribute(gemm_tf32_kernel<EPI_BIAS,      true >, cudaFuncAttributeMaxDynamicSharedMemorySize, GEMM_SMEM);
    cudaFuncSetAttribute(gemm_tf32_kernel<EPI_BIAS_RES,  false>, cudaFuncAttributeMaxDynamicSharedMemorySize, GEMM_SMEM);
    cudaFuncSetAttribute(gemm_tf32_kernel<EPI_BIAS_GELU, true >, cudaFuncAttributeMaxDynamicSharedMemorySize, GEMM_SMEM);
    cudaFuncSetAttribute(gemm_tf32_kernel<EPI_BIAS_RES2, false>, cudaFuncAttributeMaxDynamicSharedMemorySize, GEMM_SMEM);
    cudaFuncSetAttribute(flash_attn_kernel, cudaFuncAttributeMaxDynamicSharedMemorySize, FA_SMEM);

    // 0. transpose weights to k-major (once per launch; bit-exact)
    transpose_kernel<<<dim3(32, 32),  dim3(32, 8)>>>(wq, wqT, DD, DD);
    transpose_kernel<<<dim3(32, 32),  dim3(32, 8)>>>(wk, wkT, DD, DD);
    transpose_kernel<<<dim3(32, 32),  dim3(32, 8)>>>(wv, wvT, DD, DD);
    transpose_kernel<<<dim3(32, 32),  dim3(32, 8)>>>(wo, woT, DD, DD);
    transpose_kernel<<<dim3(128, 32), dim3(32, 8)>>>(w1, w1T, DD, DFF_);
    transpose_kernel<<<dim3(32, 128), dim3(32, 8)>>>(w2, w2T, DFF_, DD);
    transpose_kernel<<<dim3(32, 32),  dim3(32, 8)>>>(w3, w3T, DD, DD);

    // 1. nx = round(LN(x, g1, be1))
    ln_kernel<false><<<TOK, 256>>>(x, g1, be1, nx, nullptr);

    // 2-4. Q/K/V = round(nx @ w + b)
    gemm_tf32_kernel<EPI_BIAS, true><<<dim3(8, 32), 256, GEMM_SMEM>>>(
        nx, DD, wqT, DD, q, DD, TOK, DD, DD, bq, nullptr, nullptr);
    gemm_tf32_kernel<EPI_BIAS, true><<<dim3(8, 32), 256, GEMM_SMEM>>>(
        nx, DD, wkT, DD, k, DD, TOK, DD, DD, bk, nullptr, nullptr);
    gemm_tf32_kernel<EPI_BIAS, true><<<dim3(8, 32), 256, GEMM_SMEM>>>(
        nx, DD, wvT, DD, v, DD, TOK, DD, DD, bv, nullptr, nullptr);

    // 5. fused attention -> ctx
    flash_attn_kernel<<<dim3(8, BB * HH_), 256, FA_SMEM>>>(q, k, v, relt, ctx);

    // 6. x1 = x + ctx @ wo + bo
    gemm_tf32_kernel<EPI_BIAS_RES, false><<<dim3(8, 32), 256, GEMM_SMEM>>>(
        ctx, DD, woT, DD, x1, DD, TOK, DD, DD, bo, x, nullptr);

    // 7. nx2 = LN(x1)  (exact + rounded)
    ln_kernel<true><<<TOK, 256>>>(x1, g2, be2, nx2r, nx2e);

    // 8. ff = round(gelu(nx2 @ w1 + b1))
    gemm_tf32_kernel<EPI_BIAS_GELU, true><<<dim3(32, 32), 256, GEMM_SMEM>>>(
        nx2r, DD, w1T, DD, ff, DFF_, TOK, DFF_, DD, b1, nullptr, nullptr);

    // 9. y = nx2 + ff @ w2 + b2
    gemm_tf32_kernel<EPI_BIAS_RES, false><<<dim3(8, 32), 256, GEMM_SMEM>>>(
        ff, DFF_, w2T, DFF_, y, DD, TOK, DD, DFF_, b2, nx2e, nullptr);

    // 10. lny = round(LN(y))
    ln_kernel<false><<<TOK, 256>>>(y, gf, bf, lny, nullptr);

    // 11. out = x1 + y + lny @ w3 + b3
    gemm_tf32_kernel<EPI_BIAS_RES2, false><<<dim3(8, 32), 256, GEMM_SMEM>>>(
        lny, DD, w3T, DD, out, DD, TOK, DD, DD, b3, y, x1);
}

// round 10
// speedup vs baseline: 1.8925x; 1.8925x over previous
#include <cuda_runtime.h>
#include <cuda_fp16.h>
#include <cstdint>
#include <math.h>

// Problem constants
#define BB   4
#define SS_  1024
#define DD   1024
#define HH_  16
#define DK_  64
#define DFF_ 4096
#define TOK  (BB*SS_)          // 4096 tokens

// ---------------------------------------------------------------------------
// Scratch (static __device__ arrays — the sanctioned no-alloc mechanism)
// ---------------------------------------------------------------------------
__device__ __half g_nx  [TOK*DD];     // LN1 out (fp16, GEMM A)
__device__ float  g_q   [TOK*DD];
__device__ float  g_k   [TOK*DD];
__device__ float  g_v   [TOK*DD];
__device__ __half g_ctx [TOK*DD];     // attention out (fp16, GEMM A)
__device__ float  g_x1  [TOK*DD];
__device__ __half g_nx2r[TOK*DD];     // LN2 out fp16 (GEMM A)
__device__ float  g_nx2e[TOK*DD];     // LN2 out exact (residual)
__device__ __half g_ff  [TOK*DFF_];   // gelu out fp16 (GEMM A)
__device__ float  g_y   [TOK*DD];
__device__ __half g_lny [TOK*DD];     // LN3 out fp16 (GEMM A)
// transposed fp16 weights: wT[n][k] = (half)w[k][n]
__device__ __half g_wqT [DD*DD];
__device__ __half g_wkT [DD*DD];
__device__ __half g_wvT [DD*DD];
__device__ __half g_woT [DD*DD];
__device__ __half g_w1T [DFF_*DD];
__device__ __half g_w2T [DD*DFF_];
__device__ __half g_w3T [DD*DD];

#define DEVI __device__ __forceinline__

DEVI float f2tf32(float x) {
    uint32_t u;
    asm("cvt.rna.tf32.f32 %0, %1;" : "=r"(u) : "f"(x));
    return __uint_as_float(u);
}
DEVI float gelu_exact(float x) {
    return 0.5f * x * (1.0f + erff(x * 0.70710678118654752f));
}
DEVI void cp_async16(uint32_t dst, const void* src) {
    asm volatile("cp.async.cg.shared.global [%0], [%1], 16;\n"
                 :: "r"(dst), "l"(src));
}
DEVI void cp_commit() { asm volatile("cp.async.commit_group;\n"); }
DEVI void cp_wait1()  { asm volatile("cp.async.wait_group 1;\n"); }

// legacy tf32 mma (flash attention only)
DEVI void mma_tf32(float (&c)[4], float a0, float a1, float a2, float a3,
                   float b0, float b1) {
    asm volatile(
        "mma.sync.aligned.m16n8k8.row.col.f32.tf32.tf32.f32 "
        "{%0,%1,%2,%3}, {%4,%5,%6,%7}, {%8,%9}, {%0,%1,%2,%3};"
        : "+f"(c[0]), "+f"(c[1]), "+f"(c[2]), "+f"(c[3])
        : "r"(__float_as_uint(a0)), "r"(__float_as_uint(a1)),
          "r"(__float_as_uint(a2)), "r"(__float_as_uint(a3)),
          "r"(__float_as_uint(b0)), "r"(__float_as_uint(b1)));
}
// fp16 mma, fp32 accumulate
DEVI void mma_f16(float (&c)[4], uint32_t a0, uint32_t a1, uint32_t a2, uint32_t a3,
                  uint32_t b0, uint32_t b1) {
    asm volatile(
        "mma.sync.aligned.m16n8k16.row.col.f32.f16.f16.f32 "
        "{%0,%1,%2,%3}, {%4,%5,%6,%7}, {%8,%9}, {%0,%1,%2,%3};"
        : "+f"(c[0]), "+f"(c[1]), "+f"(c[2]), "+f"(c[3])
        : "r"(a0), "r"(a1), "r"(a2), "r"(a3), "r"(b0), "r"(b1));
}

enum { EPI_NONE = 0, EPI_BIAS = 1, EPI_BIAS_GELU = 2, EPI_BIAS_RES = 3,
       EPI_BIAS_RES2 = 4 };

// ---------------------------------------------------------------------------
// Transpose + fp32->fp16 convert: out[C][R] = (half)in[R][C]^T.
// ---------------------------------------------------------------------------
__global__ void transpose_conv_kernel(const float* __restrict__ in,
                                      __half* __restrict__ out, int R, int C)
{
    __shared__ float tile[32][33];
    const int tx = threadIdx.x, ty = threadIdx.y;
    const int r0 = blockIdx.y * 32, c0 = blockIdx.x * 32;
#pragma unroll
    for (int i = 0; i < 32; i += 8)
        tile[ty + i][tx] = in[(size_t)(r0 + ty + i) * C + c0 + tx];
    __syncthreads();
#pragma unroll
    for (int i = 0; i < 32; i += 8)
        out[(size_t)(c0 + ty + i) * R + r0 + tx] = __float2half_rn(tile[tx][ty + i]);
}

// ---------------------------------------------------------------------------
// fp16 GEMM, fp32 accumulate. CTA tile 128x128, k-tile 64 halves, 256 threads
// (8 warps, warp tile 64x32), double-buffered cp.async staging.
// A:  [M][K] half row-major (activations)
// BT: [N][K] half row-major (transposed weights)  -> mma row.col direct
// SMEM halves: A[2][128][72] @0 (2*9216), B[2][128][72] @18432.
// Total 36864 halves = 73728 bytes.
// ---------------------------------------------------------------------------
#define GEMM_SMEM 73728

template <int EPI, bool ROUND, bool OUTH>
__global__ __launch_bounds__(256, 2)
void gemm_f16_kernel(const __half* __restrict__ A, int lda,
                     const __half* __restrict__ BT, int ldbt,
                     void* __restrict__ Cout, int ldc,
                     int M, int N, int K,
                     const float* __restrict__ bias,
                     const float* __restrict__ res1,
                     const float* __restrict__ res2)
{
    extern __shared__ __half smh[];
    const uint32_t smem_u = (uint32_t)__cvta_generic_to_shared(smh);

    const int tid  = threadIdx.x;
    const int warp = tid >> 5;
    const int lane = tid & 31;
    const int wm = (warp >> 2) * 64;
    const int wn = (warp & 3) * 32;
    const int r  = lane >> 2;
    const int cq = lane & 3;

    const int blockM = blockIdx.y * 128;
    const int blockN = blockIdx.x * 128;

    float acc[4][4][4];
#pragma unroll
    for (int mt = 0; mt < 4; mt++)
#pragma unroll
        for (int nt = 0; nt < 4; nt++)
#pragma unroll
            for (int i = 0; i < 4; i++) acc[mt][nt][i] = 0.0f;

    // stage one 64-deep k-tile (A: 128x64, B: 128x64 halves) into buffer s
    auto stage = [&](int t, int s) {
        const int k0 = t << 6;
        const uint32_t abase = smem_u + (uint32_t)s * 18432u;         // bytes
        const uint32_t bbase = smem_u + 36864u + (uint32_t)s * 18432u;
#pragma unroll
        for (int i = 0; i < 4; i++) {
            int idx = tid + (i << 8);
            int row = idx >> 3;            // 0..127
            int c8  = (idx & 7) << 3;      // half offset 0..56
            uint32_t off = (uint32_t)((row * 72 + c8) * 2);
            cp_async16(abase + off, A  + (size_t)(blockM + row) * lda  + k0 + c8);
            cp_async16(bbase + off, BT + (size_t)(blockN + row) * ldbt + k0 + c8);
        }
    };

    const int T = K >> 6;
    stage(0, 0);
    cp_commit();

    for (int t = 0; t < T; t++) {
        const int cur = t & 1;
        if (t + 1 < T) stage(t + 1, cur ^ 1);
        cp_commit();
        cp_wait1();
        __syncthreads();

        const __half* Ab = smh + cur * 9216;
        const __half* Bb = smh + 18432 + cur * 9216;
#pragma unroll
        for (int kk = 0; kk < 4; kk++) {
            uint32_t av[4][4];
#pragma unroll
            for (int mt = 0; mt < 4; mt++) {
                const __half* ar0 = Ab + (wm + mt * 16 + r) * 72 + kk * 16;
                const __half* ar1 = ar0 + 8 * 72;
                av[mt][0] = *(const uint32_t*)(ar0 + 2 * cq);
                av[mt][1] = *(const uint32_t*)(ar1 + 2 * cq);
                av[mt][2] = *(const uint32_t*)(ar0 + 2 * cq + 8);
                av[mt][3] = *(const uint32_t*)(ar1 + 2 * cq + 8);
            }
#pragma unroll
            for (int nt = 0; nt < 4; nt++) {
                const __half* br = Bb + (wn + nt * 8 + r) * 72 + kk * 16;
                uint32_t b0 = *(const uint32_t*)(br + 2 * cq);
                uint32_t b1 = *(const uint32_t*)(br + 2 * cq + 8);
#pragma unroll
                for (int mt = 0; mt < 4; mt++)
                    mma_f16(acc[mt][nt], av[mt][0], av[mt][1], av[mt][2], av[mt][3],
                            b0, b1);
            }
        }
        __syncthreads();
    }

    // ---- epilogue + store ----
#pragma unroll
    for (int mt = 0; mt < 4; mt++) {
#pragma unroll
        for (int nt = 0; nt < 4; nt++) {
#pragma unroll
            for (int rh = 0; rh < 2; rh++) {
                int grow = blockM + wm + mt * 16 + r + rh * 8;
                int gcol = blockN + wn + nt * 8 + cq * 2;
                float v0 = acc[mt][nt][rh * 2 + 0];
                float v1 = acc[mt][nt][rh * 2 + 1];
                size_t cidx = (size_t)grow * ldc + gcol;
                if (EPI != EPI_NONE) {
                    v0 += bias[gcol];
                    v1 += bias[gcol + 1];
                }
                if (EPI == EPI_BIAS_GELU) { v0 = gelu_exact(v0); v1 = gelu_exact(v1); }
                if (EPI == EPI_BIAS_RES || EPI == EPI_BIAS_RES2) {
                    v0 += res1[cidx]; v1 += res1[cidx + 1];
                }
                if (EPI == EPI_BIAS_RES2) {
                    v0 += res2[cidx]; v1 += res2[cidx + 1];
                }
                if (OUTH) {
                    *(__half2*)((__half*)Cout + cidx) = __floats2half2_rn(v0, v1);
                } else {
                    if (ROUND) { v0 = f2tf32(v0); v1 = f2tf32(v1); }
                    *(float2*)((float*)Cout + cidx) = make_float2(v0, v1);
                }
            }
        }
    }
}

// ---------------------------------------------------------------------------
// Fused flash attention (R7 winner; only change: ctx output is fp16).
// SMEM floats: K[2] @ {0,4352}, V[2] @ {8704,13056}, P[w] @ 17408+w*1152,
// bias @ 26624 (128). Total 26752 floats = 107008 bytes.
// ---------------------------------------------------------------------------
#define FA_SMEM 107008

__global__ __launch_bounds__(256, 1)
void flash_attn_kernel(const float* __restrict__ Q, const float* __restrict__ K,
                       const float* __restrict__ V, const float* __restrict__ relt,
                       __half* __restrict__ ctx)
{
    extern __shared__ float sm[];
    const uint32_t sm_u = (uint32_t)__cvta_generic_to_shared(sm);

    const int tid  = threadIdx.x;
    const int warp = tid >> 5;
    const int lane = tid & 31;
    const int r  = lane >> 2;
    const int cq = lane & 3;
    const int qt = blockIdx.x;
    const int bh = blockIdx.y;
    const int b  = bh >> 4, h = bh & 15;

    const size_t base = (size_t)b * SS_ * DD + (size_t)h * DK_;
    const int qrow = qt * 128 + warp * 16 + r;

    if (tid < 127) sm[26624 + tid] = relt[tid * HH_ + h];

    const float* qp  = Q + base + (size_t)qrow * DD;
    const float* qp8 = qp + (size_t)8 * DD;
    float2 qa[8][2];
#pragma unroll
    for (int kk = 0; kk < 8; kk++) {
        float2 v0 = *(const float2*)(qp  + kk * 8 + 2 * cq);
        float2 v1 = *(const float2*)(qp8 + kk * 8 + 2 * cq);
        qa[kk][0] = make_float2(v0.x * 0.125f, v0.y * 0.125f);
        qa[kk][1] = make_float2(v1.x * 0.125f, v1.y * 0.125f);
    }

    auto stage = [&](int j, int bsel) {
#pragma unroll
        for (int i = 0; i < 4; i++) {
            int idx = tid + i * 256;
            int t   = idx >> 4;
            int sg  = (idx & 15) * 4;
            const float* kr_ = K + base + (size_t)(j * 64 + t) * DD + sg;
            const float* vr_ = V + base + (size_t)(j * 64 + t) * DD + sg;
            cp_async16(sm_u + (uint32_t)((bsel * 4352 + t * 68 + sg) * 4), kr_);
            cp_async16(sm_u + (uint32_t)(((8704 + bsel * 4352) + t * 68 + sg) * 4), vr_);
        }
    };

    float oacc[8][4];
#pragma unroll
    for (int nf = 0; nf < 8; nf++)
#pragma unroll
        for (int i = 0; i < 4; i++) oacc[nf][i] = 0.0f;
    float m0 = -3e38f, m1 = -3e38f, l0 = 0.0f, l1 = 0.0f;

    stage(0, 0);
    cp_commit();

    float* Pw = sm + 17408 + warp * 1152;
    const float* bias_sm = sm + 26624;

    for (int j = 0; j < 16; j++) {
        const int cur = j & 1;
        if (j + 1 < 16) stage(j + 1, cur ^ 1);
        cp_commit();
        cp_wait1();
        __syncthreads();

        const float* Ks = sm + cur * 4352;
        const float* Vs = sm + 8704 + cur * 4352;

        float s[8][4];
#pragma unroll
        for (int nf = 0; nf < 8; nf++)
            s[nf][0] = s[nf][1] = s[nf][2] = s[nf][3] = 0.0f;
#pragma unroll
        for (int kk = 0; kk < 8; kk++) {
#pragma unroll
            for (int nf = 0; nf < 8; nf++) {
                float2 kb = *(const float2*)(Ks + (nf * 8 + r) * 68 + kk * 8 + 2 * cq);
                mma_tf32(s[nf], qa[kk][0].x, qa[kk][1].x, qa[kk][0].y, qa[kk][1].y,
                         kb.x, kb.y);
            }
        }

        const int row0 = qrow, row1 = qrow + 8;
        const int colb = j * 64 + 2 * cq;
#pragma unroll
        for (int nf = 0; nf < 8; nf++) {
            int c0 = colb + nf * 8, c1 = c0 + 1;
            int d00 = min(max(c0 - row0 + 63, 0), 126);
            int d01 = min(max(c1 - row0 + 63, 0), 126);
            int d10 = min(max(c0 - row1 + 63, 0), 126);
            int d11 = min(max(c1 - row1 + 63, 0), 126);
            s[nf][0] += bias_sm[d00];
            s[nf][1] += bias_sm[d01];
            s[nf][2] += bias_sm[d10];
            s[nf][3] += bias_sm[d11];
        }

        float rm0 = -3e38f, rm1 = -3e38f;
#pragma unroll
        for (int nf = 0; nf < 8; nf++) {
            rm0 = fmaxf(rm0, fmaxf(s[nf][0], s[nf][1]));
            rm1 = fmaxf(rm1, fmaxf(s[nf][2], s[nf][3]));
        }
        rm0 = fmaxf(rm0, __shfl_xor_sync(0xffffffffu, rm0, 1));
        rm0 = fmaxf(rm0, __shfl_xor_sync(0xffffffffu, rm0, 2));
        rm1 = fmaxf(rm1, __shfl_xor_sync(0xffffffffu, rm1, 1));
        rm1 = fmaxf(rm1, __shfl_xor_sync(0xffffffffu, rm1, 2));
        float mn0 = fmaxf(m0, rm0), mn1 = fmaxf(m1, rm1);
        float a0 = __expf(m0 - mn0), a1 = __expf(m1 - mn1);
        m0 = mn0; m1 = mn1;
        float sum0 = 0.0f, sum1 = 0.0f;
#pragma unroll
        for (int nf = 0; nf < 8; nf++) {
            s[nf][0] = __expf(s[nf][0] - mn0);
            s[nf][1] = __expf(s[nf][1] - mn0);
            s[nf][2] = __expf(s[nf][2] - mn1);
            s[nf][3] = __expf(s[nf][3] - mn1);
            sum0 += s[nf][0] + s[nf][1];
            sum1 += s[nf][2] + s[nf][3];
        }
        sum0 += __shfl_xor_sync(0xffffffffu, sum0, 1);
        sum0 += __shfl_xor_sync(0xffffffffu, sum0, 2);
        sum1 += __shfl_xor_sync(0xffffffffu, sum1, 1);
        sum1 += __shfl_xor_sync(0xffffffffu, sum1, 2);
        l0 = l0 * a0 + sum0;
        l1 = l1 * a1 + sum1;
#pragma unroll
        for (int nf = 0; nf < 8; nf++) {
            oacc[nf][0] *= a0; oacc[nf][1] *= a0;
            oacc[nf][2] *= a1; oacc[nf][3] *= a1;
        }

#pragma unroll
        for (int nf = 0; nf < 8; nf++) {
            *(float2*)(Pw + r * 72 + nf * 8 + 2 * cq) =
                make_float2(f2tf32(s[nf][0]), f2tf32(s[nf][1]));
            *(float2*)(Pw + (r + 8) * 72 + nf * 8 + 2 * cq) =
                make_float2(f2tf32(s[nf][2]), f2tf32(s[nf][3]));
        }
        __syncwarp();

#pragma unroll
        for (int kk = 0; kk < 8; kk++) {
            float2 pa0 = *(const float2*)(Pw + r * 72 + kk * 8 + 2 * cq);
            float2 pa1 = *(const float2*)(Pw + (r + 8) * 72 + kk * 8 + 2 * cq);
#pragma unroll
            for (int nf = 0; nf < 8; nf++) {
                float vb0 = Vs[(kk * 8 + 2 * cq    ) * 68 + nf * 8 + r];
                float vb1 = Vs[(kk * 8 + 2 * cq + 1) * 68 + nf * 8 + r];
                mma_tf32(oacc[nf], pa0.x, pa1.x, pa0.y, pa1.y, vb0, vb1);
            }
        }
        __syncthreads();
    }

    const float inv0 = 1.0f / l0, inv1 = 1.0f / l1;
    __half* op  = ctx + base + (size_t)qrow * DD;
    __half* op8 = op + (size_t)8 * DD;
#pragma unroll
    for (int nf = 0; nf < 8; nf++) {
        *(__half2*)(op + nf * 8 + 2 * cq) =
            __floats2half2_rn(oacc[nf][0] * inv0, oacc[nf][1] * inv0);
        *(__half2*)(op8 + nf * 8 + 2 * cq) =
            __floats2half2_rn(oacc[nf][2] * inv1, oacc[nf][3] * inv1);
    }
}

// ---------------------------------------------------------------------------
// LayerNorm: fp16 output for GEMM A; optional exact fp32 output.
// ---------------------------------------------------------------------------
template <bool DUAL>
__global__ void ln_kernel(const float* __restrict__ x, const float* __restrict__ g,
                          const float* __restrict__ b,
                          __half* __restrict__ out_r, float* __restrict__ out_e)
{
    __shared__ float sb[8];
    const int row = blockIdx.x;
    const int t   = threadIdx.x;
    float4 v = ((const float4*)(x + (size_t)row * DD))[t];

    float s = v.x + v.y + v.z + v.w;
#pragma unroll
    for (int o = 16; o; o >>= 1) s += __shfl_xor_sync(0xffffffffu, s, o);
    if ((t & 31) == 0) sb[t >> 5] = s;
    __syncthreads();
    float mean = (sb[0]+sb[1]+sb[2]+sb[3]+sb[4]+sb[5]+sb[6]+sb[7]) * (1.0f / DD);
    __syncthreads();

    float d0 = v.x - mean, d1 = v.y - mean, d2 = v.z - mean, d3 = v.w - mean;
    float s2 = d0*d0 + d1*d1 + d2*d2 + d3*d3;
#pragma unroll
    for (int o = 16; o; o >>= 1) s2 += __shfl_xor_sync(0xffffffffu, s2, o);
    if ((t & 31) == 0) sb[t >> 5] = s2;
    __syncthreads();
    float var = (sb[0]+sb[1]+sb[2]+sb[3]+sb[4]+sb[5]+sb[6]+sb[7]) * (1.0f / DD);
    float inv = rsqrtf(var + 1e-5f);

    float4 gv = ((const float4*)g)[t];
    float4 bv = ((const float4*)b)[t];
    float4 o4 = make_float4(d0 * inv * gv.x + bv.x, d1 * inv * gv.y + bv.y,
                            d2 * inv * gv.z + bv.z, d3 * inv * gv.w + bv.w);
    if (DUAL)
        ((float4*)(out_e + (size_t)row * DD))[t] = o4;
    __half* p = out_r + (size_t)row * DD + 4 * t;
    *(__half2*)p       = __floats2half2_rn(o4.x, o4.y);
    *(__half2*)(p + 2) = __floats2half2_rn(o4.z, o4.w);
}

// ---------------------------------------------------------------------------
// Launch
// ---------------------------------------------------------------------------
extern "C" void kernel_launch(void* const* d_in, const int* in_sizes, int n_in,
                              void* d_out, int out_size)
{
    (void)in_sizes; (void)n_in; (void)out_size;
    const float* x    = (const float*)d_in[0];
    const float* wq   = (const float*)d_in[1];
    const float* bq   = (const float*)d_in[2];
    const float* wk   = (const float*)d_in[3];
    const float* bk   = (const float*)d_in[4];
    const float* wv   = (const float*)d_in[5];
    const float* bv   = (const float*)d_in[6];
    const float* wo   = (const float*)d_in[7];
    const float* bo   = (const float*)d_in[8];
    const float* relt = (const float*)d_in[9];
    const float* g1   = (const float*)d_in[10];
    const float* be1  = (const float*)d_in[11];
    const float* g2   = (const float*)d_in[12];
    const float* be2  = (const float*)d_in[13];
    const float* w1   = (const float*)d_in[14];
    const float* b1   = (const float*)d_in[15];
    const float* w2   = (const float*)d_in[16];
    const float* b2   = (const float*)d_in[17];
    const float* w3   = (const float*)d_in[18];
    const float* b3   = (const float*)d_in[19];
    const float* gf   = (const float*)d_in[20];
    const float* bf   = (const float*)d_in[21];
    float* out = (float*)d_out;

    __half *nx, *ctx, *nx2r, *ff, *lny;
    float  *q, *k, *v, *x1, *nx2e, *y;
    __half *wqT, *wkT, *wvT, *woT, *w1T, *w2T, *w3T;
    cudaGetSymbolAddress((void**)&nx,   g_nx);
    cudaGetSymbolAddress((void**)&q,    g_q);
    cudaGetSymbolAddress((void**)&k,    g_k);
    cudaGetSymbolAddress((void**)&v,    g_v);
    cudaGetSymbolAddress((void**)&ctx,  g_ctx);
    cudaGetSymbolAddress((void**)&x1,   g_x1);
    cudaGetSymbolAddress((void**)&nx2r, g_nx2r);
    cudaGetSymbolAddress((void**)&nx2e, g_nx2e);
    cudaGetSymbolAddress((void**)&ff,   g_ff);
    cudaGetSymbolAddress((void**)&y,    g_y);
    cudaGetSymbolAddress((void**)&lny,  g_lny);
    cudaGetSymbolAddress((void**)&wqT,  g_wqT);
    cudaGetSymbolAddress((void**)&wkT,  g_wkT);
    cudaGetSymbolAddress((void**)&wvT,  g_wvT);
    cudaGetSymbolAddress((void**)&woT,  g_woT);
    cudaGetSymbolAddress((void**)&w1T,  g_w1T);
    cudaGetSymbolAddress((void**)&w2T,  g_w2T);
    cudaGetSymbolAddress((void**)&w3T,  g_w3T);

    cudaFuncSetAttribute(gemm_f16_kernel<EPI_BIAS,      true,  false>, cudaFuncAttributeMaxDynamicSharedMemorySize, GEMM_SMEM);
    cudaFuncSetAttribute(gemm_f16_kernel<EPI_BIAS_RES,  false, false>, cudaFuncAttributeMaxDynamicSharedMemorySize, GEMM_SMEM);
    cudaFuncSetAttribute(gemm_f16_kernel<EPI_BIAS_GELU, false, true >, cudaFuncAttributeMaxDynamicSharedMemorySize, GEMM_SMEM);
    cudaFuncSetAttribute(gemm_f16_kernel<EPI_BIAS_RES2, false, false>, cudaFuncAttributeMaxDynamicSharedMemorySize, GEMM_SMEM);
    cudaFuncSetAttribute(flash_attn_kernel, cudaFuncAttributeMaxDynamicSharedMemorySize, FA_SMEM);

    // 0. transpose + fp16-convert weights
    transpose_conv_kernel<<<dim3(32, 32),  dim3(32, 8)>>>(wq, wqT, DD, DD);
    transpose_conv_kernel<<<dim3(32, 32),  dim3(32, 8)>>>(wk, wkT, DD, DD);
    transpose_conv_kernel<<<dim3(32, 32),  dim3(32, 8)>>>(wv, wvT, DD, DD);
    transpose_conv_kernel<<<dim3(32, 32),  dim3(32, 8)>>>(wo, woT, DD, DD);
    transpose_conv_kernel<<<dim3(128, 32), dim3(32, 8)>>>(w1, w1T, DD, DFF_);
    transpose_conv_kernel<<<dim3(32, 128), dim3(32, 8)>>>(w2, w2T, DFF_, DD);
    transpose_conv_kernel<<<dim3(32, 32),  dim3(32, 8)>>>(w3, w3T, DD, DD);

    // 1. nx = (half)LN(x, g1, be1)
    ln_kernel<false><<<TOK, 256>>>(x, g1, be1, nx, nullptr);

    // 2-4. Q/K/V = round_tf32(nx @ w + b)  (fp32 out, feeds flash)
    gemm_f16_kernel<EPI_BIAS, true, false><<<dim3(8, 32), 256, GEMM_SMEM>>>(
        nx, DD, wqT, DD, q, DD, TOK, DD, DD, bq, nullptr, nullptr);
    gemm_f16_kernel<EPI_BIAS, true, false><<<dim3(8, 32), 256, GEMM_SMEM>>>(
        nx, DD, wkT, DD, k, DD, TOK, DD, DD, bk, nullptr, nullptr);
    gemm_f16_kernel<EPI_BIAS, true, false><<<dim3(8, 32), 256, GEMM_SMEM>>>(
        nx, DD, wvT, DD, v, DD, TOK, DD, DD, bv, nullptr, nullptr);

    // 5. fused attention -> ctx (fp16)
    flash_attn_kernel<<<dim3(8, BB * HH_), 256, FA_SMEM>>>(q, k, v, relt, ctx);

    // 6. x1 = x + ctx @ wo + bo
    gemm_f16_kernel<EPI_BIAS_RES, false, false><<<dim3(8, 32), 256, GEMM_SMEM>>>(
        ctx, DD, woT, DD, x1, DD, TOK, DD, DD, bo, x, nullptr);

    // 7. nx2 = LN(x1)  (half + exact fp32)
    ln_kernel<true><<<TOK, 256>>>(x1, g2, be2, nx2r, nx2e);

    // 8. ff = (half)gelu(nx2 @ w1 + b1)
    gemm_f16_kernel<EPI_BIAS_GELU, false, true><<<dim3(32, 32), 256, GEMM_SMEM>>>(
        nx2r, DD, w1T, DD, ff, DFF_, TOK, DFF_, DD, b1, nullptr, nullptr);

    // 9. y = nx2 + ff @ w2 + b2
    gemm_f16_kernel<EPI_BIAS_RES, false, false><<<dim3(8, 32), 256, GEMM_SMEM>>>(
        ff, DFF_, w2T, DFF_, y, DD, TOK, DD, DFF_, b2, nx2e, nullptr);

    // 10. lny = (half)LN(y)
    ln_kernel<false><<<TOK, 256>>>(y, gf, bf, lny, nullptr);

    // 11. out = x1 + y + lny @ w3 + b3
    gemm_f16_kernel<EPI_BIAS_RES2, false, false><<<dim3(8, 32), 256, GEMM_SMEM>>>(
        lny, DD, w3T, DD, out, DD, TOK, DD, DD, b3, y, x1);
}

// round 11
// speedup vs baseline: 2.3819x; 1.2586x over previous
#include <cuda_runtime.h>
#include <cuda_fp16.h>
#include <cstdint>
#include <math.h>

// Problem constants
#define BB   4
#define SS_  1024
#define DD   1024
#define HH_  16
#define DK_  64
#define DFF_ 4096
#define TOK  (BB*SS_)          // 4096 tokens

// ---------------------------------------------------------------------------
// Scratch (static __device__ arrays — the sanctioned no-alloc mechanism)
// ---------------------------------------------------------------------------
__device__ __half g_nx  [TOK*DD];     // LN1 out (fp16)
__device__ __half g_q   [TOK*DD];     // fp16 now
__device__ __half g_k   [TOK*DD];
__device__ __half g_v   [TOK*DD];
__device__ __half g_ctx [TOK*DD];
__device__ float  g_x1  [TOK*DD];
__device__ __half g_nx2r[TOK*DD];
__device__ float  g_nx2e[TOK*DD];
__device__ __half g_ff  [TOK*DFF_];
__device__ float  g_y   [TOK*DD];
__device__ __half g_lny [TOK*DD];
// transposed fp16 weights: wT[n][k] = (half)w[k][n]
__device__ __half g_wqT [DD*DD];
__device__ __half g_wkT [DD*DD];
__device__ __half g_wvT [DD*DD];
__device__ __half g_woT [DD*DD];
__device__ __half g_w1T [DFF_*DD];
__device__ __half g_w2T [DD*DFF_];
__device__ __half g_w3T [DD*DD];

#define DEVI __device__ __forceinline__

DEVI float gelu_exact(float x) {
    return 0.5f * x * (1.0f + erff(x * 0.70710678118654752f));
}
DEVI void cp_async16(uint32_t dst, const void* src) {
    asm volatile("cp.async.cg.shared.global [%0], [%1], 16;\n"
                 :: "r"(dst), "l"(src));
}
DEVI void cp_commit() { asm volatile("cp.async.commit_group;\n"); }
DEVI void cp_wait1()  { asm volatile("cp.async.wait_group 1;\n"); }

// fp16 mma, fp32 accumulate
DEVI void mma_f16(float (&c)[4], uint32_t a0, uint32_t a1, uint32_t a2, uint32_t a3,
                  uint32_t b0, uint32_t b1) {
    asm volatile(
        "mma.sync.aligned.m16n8k16.row.col.f32.f16.f16.f32 "
        "{%0,%1,%2,%3}, {%4,%5,%6,%7}, {%8,%9}, {%0,%1,%2,%3};"
        : "+f"(c[0]), "+f"(c[1]), "+f"(c[2]), "+f"(c[3])
        : "r"(a0), "r"(a1), "r"(a2), "r"(a3), "r"(b0), "r"(b1));
}
DEVI void ldm_x4(uint32_t* r, uint32_t addr) {
    asm volatile("ldmatrix.sync.aligned.m8n8.x4.shared.b16 {%0,%1,%2,%3}, [%4];"
                 : "=r"(r[0]), "=r"(r[1]), "=r"(r[2]), "=r"(r[3]) : "r"(addr));
}
DEVI void ldm_x4_trans(uint32_t* r, uint32_t addr) {
    asm volatile("ldmatrix.sync.aligned.m8n8.x4.trans.shared.b16 {%0,%1,%2,%3}, [%4];"
                 : "=r"(r[0]), "=r"(r[1]), "=r"(r[2]), "=r"(r[3]) : "r"(addr));
}

enum { EPI_NONE = 0, EPI_BIAS = 1, EPI_BIAS_GELU = 2, EPI_BIAS_RES = 3,
       EPI_BIAS_RES2 = 4 };

// ---------------------------------------------------------------------------
// Transpose + fp32->fp16 convert: out[C][R] = (half)in[R][C]^T.
// ---------------------------------------------------------------------------
__global__ void transpose_conv_kernel(const float* __restrict__ in,
                                      __half* __restrict__ out, int R, int C)
{
    __shared__ float tile[32][33];
    const int tx = threadIdx.x, ty = threadIdx.y;
    const int r0 = blockIdx.y * 32, c0 = blockIdx.x * 32;
#pragma unroll
    for (int i = 0; i < 32; i += 8)
        tile[ty + i][tx] = in[(size_t)(r0 + ty + i) * C + c0 + tx];
    __syncthreads();
#pragma unroll
    for (int i = 0; i < 32; i += 8)
        out[(size_t)(c0 + ty + i) * R + r0 + tx] = __float2half_rn(tile[tx][ty + i]);
}

// ---------------------------------------------------------------------------
// fp16 GEMM, fp32 accumulate. CTA tile 128x128, k-tile 64 halves, 256 threads
// (8 warps, warp tile 64x32), double-buffered cp.async, ldmatrix frag loads.
// A:  [M][K] half row-major;  BT: [N][K] half row-major.
// SMEM halves: A[2][128][72] @0, B[2][128][72] @18432. 73728 bytes.
// ---------------------------------------------------------------------------
#define GEMM_SMEM 73728

template <int EPI, bool OUTH>
__global__ __launch_bounds__(256, 2)
void gemm_f16_kernel(const __half* __restrict__ A, int lda,
                     const __half* __restrict__ BT, int ldbt,
                     void* __restrict__ Cout, int ldc,
                     int M, int N, int K,
                     const float* __restrict__ bias,
                     const float* __restrict__ res1,
                     const float* __restrict__ res2)
{
    extern __shared__ __half smh[];
    const uint32_t smem_u = (uint32_t)__cvta_generic_to_shared(smh);

    const int tid  = threadIdx.x;
    const int warp = tid >> 5;
    const int lane = tid & 31;
    const int wm = (warp >> 2) * 64;
    const int wn = (warp & 3) * 32;
    const int r  = lane >> 2;
    const int cq = lane & 3;

    // ldmatrix per-lane offsets (bytes)
    const uint32_t a_off = (uint32_t)(((wm + (lane & 15)) * 72 + (lane >> 4) * 8) * 2);
    const uint32_t b_off = (uint32_t)(((wn + (lane & 7) + ((lane >> 4) << 3)) * 72
                                       + ((lane >> 3) & 1) * 8) * 2);

    const int blockM = blockIdx.y * 128;
    const int blockN = blockIdx.x * 128;

    float acc[4][4][4];
#pragma unroll
    for (int mt = 0; mt < 4; mt++)
#pragma unroll
        for (int nt = 0; nt < 4; nt++)
#pragma unroll
            for (int i = 0; i < 4; i++) acc[mt][nt][i] = 0.0f;

    auto stage = [&](int t, int s) {
        const int k0 = t << 6;
        const uint32_t abase = smem_u + (uint32_t)s * 18432u;
        const uint32_t bbase = smem_u + 36864u + (uint32_t)s * 18432u;
#pragma unroll
        for (int i = 0; i < 4; i++) {
            int idx = tid + (i << 8);
            int row = idx >> 3;
            int c8  = (idx & 7) << 3;
            uint32_t off = (uint32_t)((row * 72 + c8) * 2);
            cp_async16(abase + off, A  + (size_t)(blockM + row) * lda  + k0 + c8);
            cp_async16(bbase + off, BT + (size_t)(blockN + row) * ldbt + k0 + c8);
        }
    };

    const int T = K >> 6;
    stage(0, 0);
    cp_commit();

    for (int t = 0; t < T; t++) {
        const int cur = t & 1;
        if (t + 1 < T) stage(t + 1, cur ^ 1);
        cp_commit();
        cp_wait1();
        __syncthreads();

        const uint32_t ab = smem_u + (uint32_t)cur * 18432u;
        const uint32_t bb = smem_u + 36864u + (uint32_t)cur * 18432u;
#pragma unroll
        for (int kk = 0; kk < 4; kk++) {
            uint32_t av[4][4];
#pragma unroll
            for (int mt = 0; mt < 4; mt++)
                ldm_x4(av[mt], ab + a_off + mt * 2304u + kk * 32u);
            uint32_t bv[8];
            ldm_x4(bv,     bb + b_off + kk * 32u);
            ldm_x4(bv + 4, bb + b_off + 2304u + kk * 32u);
#pragma unroll
            for (int nt = 0; nt < 4; nt++)
#pragma unroll
                for (int mt = 0; mt < 4; mt++)
                    mma_f16(acc[mt][nt], av[mt][0], av[mt][1], av[mt][2], av[mt][3],
                            bv[2 * nt], bv[2 * nt + 1]);
        }
        __syncthreads();
    }

    // ---- epilogue + store ----
#pragma unroll
    for (int mt = 0; mt < 4; mt++) {
#pragma unroll
        for (int nt = 0; nt < 4; nt++) {
#pragma unroll
            for (int rh = 0; rh < 2; rh++) {
                int grow = blockM + wm + mt * 16 + r + rh * 8;
                int gcol = blockN + wn + nt * 8 + cq * 2;
                float v0 = acc[mt][nt][rh * 2 + 0];
                float v1 = acc[mt][nt][rh * 2 + 1];
                size_t cidx = (size_t)grow * ldc + gcol;
                if (EPI != EPI_NONE) {
                    v0 += bias[gcol];
                    v1 += bias[gcol + 1];
                }
                if (EPI == EPI_BIAS_GELU) { v0 = gelu_exact(v0); v1 = gelu_exact(v1); }
                if (EPI == EPI_BIAS_RES || EPI == EPI_BIAS_RES2) {
                    v0 += res1[cidx]; v1 += res1[cidx + 1];
                }
                if (EPI == EPI_BIAS_RES2) {
                    v0 += res2[cidx]; v1 += res2[cidx + 1];
                }
                if (OUTH) {
                    *(__half2*)((__half*)Cout + cidx) = __floats2half2_rn(v0, v1);
                } else {
                    *(float2*)((float*)Cout + cidx) = make_float2(v0, v1);
                }
            }
        }
    }
}

// ---------------------------------------------------------------------------
// Fused flash attention, full fp16 operands, fp32 accum/softmax.
// Grid (8 q-tiles, B*H), 256 threads = 8 warps, 2 CTAs/SM.
// SMEM halves: K[2][64][72] @0, V[2][64][72] @9216, P[8][16][72] @18432,
// bias fp32[128] @27648. Total 55808 bytes.
// ---------------------------------------------------------------------------
#define FA_SMEM 55808

__global__ __launch_bounds__(256, 2)
void flash_attn_kernel(const __half* __restrict__ Q, const __half* __restrict__ K,
                       const __half* __restrict__ V, const float* __restrict__ relt,
                       __half* __restrict__ ctx)
{
    extern __shared__ __half smh[];
    const uint32_t sm_u = (uint32_t)__cvta_generic_to_shared(smh);

    const int tid  = threadIdx.x;
    const int warp = tid >> 5;
    const int lane = tid & 31;
    const int r  = lane >> 2;
    const int cq = lane & 3;
    const int qt = blockIdx.x;
    const int bh = blockIdx.y;
    const int b  = bh >> 4, h = bh & 15;

    const size_t base = (size_t)b * SS_ * DD + (size_t)h * DK_;
    const int qrow = qt * 128 + warp * 16 + r;

    float* bias_sm = (float*)(smh + 27648);
    if (tid < 127) bias_sm[tid] = relt[tid * HH_ + h];

    // ldmatrix per-lane offsets (bytes)
    const uint32_t kb_off = (uint32_t)((((lane & 7) + ((lane >> 4) << 3)) * 72
                                        + ((lane >> 3) & 1) * 8) * 2);
    const int v_row = (lane & 7) + ((lane >> 3) & 1) * 8;
    const int v_d8  = (lane >> 4) * 8;

    // Q fragments in registers (fp16)
    const __half* qp  = Q + base + (size_t)qrow * DD;
    const __half* qp8 = qp + (size_t)8 * DD;
    uint32_t qa[4][4];
#pragma unroll
    for (int kk = 0; kk < 4; kk++) {
        qa[kk][0] = *(const uint32_t*)(qp  + kk * 16 + 2 * cq);
        qa[kk][1] = *(const uint32_t*)(qp8 + kk * 16 + 2 * cq);
        qa[kk][2] = *(const uint32_t*)(qp  + kk * 16 + 2 * cq + 8);
        qa[kk][3] = *(const uint32_t*)(qp8 + kk * 16 + 2 * cq + 8);
    }

    auto stage = [&](int j, int bsel) {
#pragma unroll
        for (int i = 0; i < 2; i++) {
            int idx = tid + (i << 8);           // 0..511
            int t   = idx >> 3;                 // 0..63
            int c8  = (idx & 7) << 3;           // 0..56 halves
            uint32_t off = (uint32_t)((t * 72 + c8) * 2);
            cp_async16(sm_u + (uint32_t)bsel * 9216u + off,
                       K + base + (size_t)(j * 64 + t) * DD + c8);
            cp_async16(sm_u + 18432u + (uint32_t)bsel * 9216u + off,
                       V + base + (size_t)(j * 64 + t) * DD + c8);
        }
    };

    float oacc[8][4];
#pragma unroll
    for (int nf = 0; nf < 8; nf++)
#pragma unroll
        for (int i = 0; i < 4; i++) oacc[nf][i] = 0.0f;
    float m0 = -3e38f, m1 = -3e38f, l0 = 0.0f, l1 = 0.0f;

    stage(0, 0);
    cp_commit();

    __half* Pw = smh + 18432 + warp * 1152;

    for (int j = 0; j < 16; j++) {
        const int cur = j & 1;
        if (j + 1 < 16) stage(j + 1, cur ^ 1);
        cp_commit();
        cp_wait1();
        __syncthreads();

        const uint32_t k_u = sm_u + (uint32_t)cur * 9216u;
        const uint32_t v_u = sm_u + 18432u + (uint32_t)cur * 9216u;

        // ---- S = Q @ K^T : 16x64 per warp, fp16 mma ----
        float s[8][4];
#pragma unroll
        for (int nf = 0; nf < 8; nf++)
            s[nf][0] = s[nf][1] = s[nf][2] = s[nf][3] = 0.0f;
#pragma unroll
        for (int kk = 0; kk < 4; kk++) {
            uint32_t kb[16];
#pragma unroll
            for (int p = 0; p < 4; p++)
                ldm_x4(kb + 4 * p, k_u + kb_off + p * 2304u + kk * 32u);
#pragma unroll
            for (int nf = 0; nf < 8; nf++)
                mma_f16(s[nf], qa[kk][0], qa[kk][1], qa[kk][2], qa[kk][3],
                        kb[2 * nf], kb[2 * nf + 1]);
        }

        // ---- scale (1/8) + rel-position bias ----
        const int row0 = qrow, row1 = qrow + 8;
#pragma unroll
        for (int nf = 0; nf < 8; nf++) {
            int c0 = j * 64 + nf * 8 + 2 * cq, c1 = c0 + 1;
            int d00 = min(max(c0 - row0 + 63, 0), 126);
            int d01 = min(max(c1 - row0 + 63, 0), 126);
            int d10 = min(max(c0 - row1 + 63, 0), 126);
            int d11 = min(max(c1 - row1 + 63, 0), 126);
            s[nf][0] = s[nf][0] * 0.125f + bias_sm[d00];
            s[nf][1] = s[nf][1] * 0.125f + bias_sm[d01];
            s[nf][2] = s[nf][2] * 0.125f + bias_sm[d10];
            s[nf][3] = s[nf][3] * 0.125f + bias_sm[d11];
        }

        // ---- online softmax ----
        float rm0 = -3e38f, rm1 = -3e38f;
#pragma unroll
        for (int nf = 0; nf < 8; nf++) {
            rm0 = fmaxf(rm0, fmaxf(s[nf][0], s[nf][1]));
            rm1 = fmaxf(rm1, fmaxf(s[nf][2], s[nf][3]));
        }
        rm0 = fmaxf(rm0, __shfl_xor_sync(0xffffffffu, rm0, 1));
        rm0 = fmaxf(rm0, __shfl_xor_sync(0xffffffffu, rm0, 2));
        rm1 = fmaxf(rm1, __shfl_xor_sync(0xffffffffu, rm1, 1));
        rm1 = fmaxf(rm1, __shfl_xor_sync(0xffffffffu, rm1, 2));
        float mn0 = fmaxf(m0, rm0), mn1 = fmaxf(m1, rm1);
        float a0 = __expf(m0 - mn0), a1 = __expf(m1 - mn1);
        m0 = mn0; m1 = mn1;
        float sum0 = 0.0f, sum1 = 0.0f;
#pragma unroll
        for (int nf = 0; nf < 8; nf++) {
            s[nf][0] = __expf(s[nf][0] - mn0);
            s[nf][1] = __expf(s[nf][1] - mn0);
            s[nf][2] = __expf(s[nf][2] - mn1);
            s[nf][3] = __expf(s[nf][3] - mn1);
            sum0 += s[nf][0] + s[nf][1];
            sum1 += s[nf][2] + s[nf][3];
        }
        sum0 += __shfl_xor_sync(0xffffffffu, sum0, 1);
        sum0 += __shfl_xor_sync(0xffffffffu, sum0, 2);
        sum1 += __shfl_xor_sync(0xffffffffu, sum1, 1);
        sum1 += __shfl_xor_sync(0xffffffffu, sum1, 2);
        l0 = l0 * a0 + sum0;
        l1 = l1 * a1 + sum1;
#pragma unroll
        for (int nf = 0; nf < 8; nf++) {
            oacc[nf][0] *= a0; oacc[nf][1] *= a0;
            oacc[nf][2] *= a1; oacc[nf][3] *= a1;
        }

        // ---- P (fp16) via warp-private SMEM ----
#pragma unroll
        for (int nf = 0; nf < 8; nf++) {
            *(__half2*)(Pw + r * 72 + nf * 8 + 2 * cq) =
                __floats2half2_rn(s[nf][0], s[nf][1]);
            *(__half2*)(Pw + (r + 8) * 72 + nf * 8 + 2 * cq) =
                __floats2half2_rn(s[nf][2], s[nf][3]);
        }
        __syncwarp();

        // ---- O += P @ V (fp16 mma, V via ldmatrix.trans) ----
#pragma unroll
        for (int kk = 0; kk < 4; kk++) {
            uint32_t pa[4];
            pa[0] = *(const uint32_t*)(Pw + r * 72       + kk * 16 + 2 * cq);
            pa[1] = *(const uint32_t*)(Pw + (r + 8) * 72 + kk * 16 + 2 * cq);
            pa[2] = *(const uint32_t*)(Pw + r * 72       + kk * 16 + 2 * cq + 8);
            pa[3] = *(const uint32_t*)(Pw + (r + 8) * 72 + kk * 16 + 2 * cq + 8);
            uint32_t vb[16];
#pragma unroll
            for (int p = 0; p < 4; p++)
                ldm_x4_trans(vb + 4 * p,
                    v_u + (uint32_t)(((kk * 16 + v_row) * 72 + p * 16 + v_d8) * 2));
#pragma unroll
            for (int nf = 0; nf < 8; nf++)
                mma_f16(oacc[nf], pa[0], pa[1], pa[2], pa[3],
                        vb[2 * nf], vb[2 * nf + 1]);
        }
        __syncthreads();
    }

    // ---- epilogue: normalize + store ctx (fp16) ----
    const float inv0 = 1.0f / l0, inv1 = 1.0f / l1;
    __half* op  = ctx + base + (size_t)qrow * DD;
    __half* op8 = op + (size_t)8 * DD;
#pragma unroll
    for (int nf = 0; nf < 8; nf++) {
        *(__half2*)(op + nf * 8 + 2 * cq) =
            __floats2half2_rn(oacc[nf][0] * inv0, oacc[nf][1] * inv0);
        *(__half2*)(op8 + nf * 8 + 2 * cq) =
            __floats2half2_rn(oacc[nf][2] * inv1, oacc[nf][3] * inv1);
    }
}

// ---------------------------------------------------------------------------
// LayerNorm: fp16 output for GEMM A; optional exact fp32 output.
// ---------------------------------------------------------------------------
template <bool DUAL>
__global__ void ln_kernel(const float* __restrict__ x, const float* __restrict__ g,
                          const float* __restrict__ b,
                          __half* __restrict__ out_r, float* __restrict__ out_e)
{
    __shared__ float sb[8];
    const int row = blockIdx.x;
    const int t   = threadIdx.x;
    float4 v = ((const float4*)(x + (size_t)row * DD))[t];

    float s = v.x + v.y + v.z + v.w;
#pragma unroll
    for (int o = 16; o; o >>= 1) s += __shfl_xor_sync(0xffffffffu, s, o);
    if ((t & 31) == 0) sb[t >> 5] = s;
    __syncthreads();
    float mean = (sb[0]+sb[1]+sb[2]+sb[3]+sb[4]+sb[5]+sb[6]+sb[7]) * (1.0f / DD);
    __syncthreads();

    float d0 = v.x - mean, d1 = v.y - mean, d2 = v.z - mean, d3 = v.w - mean;
    float s2 = d0*d0 + d1*d1 + d2*d2 + d3*d3;
#pragma unroll
    for (int o = 16; o; o >>= 1) s2 += __shfl_xor_sync(0xffffffffu, s2, o);
    if ((t & 31) == 0) sb[t >> 5] = s2;
    __syncthreads();
    float var = (sb[0]+sb[1]+sb[2]+sb[3]+sb[4]+sb[5]+sb[6]+sb[7]) * (1.0f / DD);
    float inv = rsqrtf(var + 1e-5f);

    float4 gv = ((const float4*)g)[t];
    float4 bv = ((const float4*)b)[t];
    float4 o4 = make_float4(d0 * inv * gv.x + bv.x, d1 * inv * gv.y + bv.y,
                            d2 * inv * gv.z + bv.z, d3 * inv * gv.w + bv.w);
    if (DUAL)
        ((float4*)(out_e + (size_t)row * DD))[t] = o4;
    __half* p = out_r + (size_t)row * DD + 4 * t;
    *(__half2*)p       = __floats2half2_rn(o4.x, o4.y);
    *(__half2*)(p + 2) = __floats2half2_rn(o4.z, o4.w);
}

// ---------------------------------------------------------------------------
// Launch (ordered so ncu's "-s 5 -c 1" captures gemm_q at launch index 5)
// ---------------------------------------------------------------------------
extern "C" void kernel_launch(void* const* d_in, const int* in_sizes, int n_in,
                              void* d_out, int out_size)
{
    (void)in_sizes; (void)n_in; (void)out_size;
    const float* x    = (const float*)d_in[0];
    const float* wq   = (const float*)d_in[1];
    const float* bq   = (const float*)d_in[2];
    const float* wk   = (const float*)d_in[3];
    const float* bk   = (const float*)d_in[4];
    const float* wv   = (const float*)d_in[5];
    const float* bv   = (const float*)d_in[6];
    const float* wo   = (const float*)d_in[7];
    const float* bo   = (const float*)d_in[8];
    const float* relt = (const float*)d_in[9];
    const float* g1   = (const float*)d_in[10];
    const float* be1  = (const float*)d_in[11];
    const float* g2   = (const float*)d_in[12];
    const float* be2  = (const float*)d_in[13];
    const float* w1   = (const float*)d_in[14];
    const float* b1   = (const float*)d_in[15];
    const float* w2   = (const float*)d_in[16];
    const float* b2   = (const float*)d_in[17];
    const float* w3   = (const float*)d_in[18];
    const float* b3   = (const float*)d_in[19];
    const float* gf   = (const float*)d_in[20];
    const float* bf   = (const float*)d_in[21];
    float* out = (float*)d_out;

    __half *nx, *q, *k, *v, *ctx, *nx2r, *ff, *lny;
    float  *x1, *nx2e, *y;
    __half *wqT, *wkT, *wvT, *woT, *w1T, *w2T, *w3T;
    cudaGetSymbolAddress((void**)&nx,   g_nx);
    cudaGetSymbolAddress((void**)&q,    g_q);
    cudaGetSymbolAddress((void**)&k,    g_k);
    cudaGetSymbolAddress((void**)&v,    g_v);
    cudaGetSymbolAddress((void**)&ctx,  g_ctx);
    cudaGetSymbolAddress((void**)&x1,   g_x1);
    cudaGetSymbolAddress((void**)&nx2r, g_nx2r);
    cudaGetSymbolAddress((void**)&nx2e, g_nx2e);
    cudaGetSymbolAddress((void**)&ff,   g_ff);
    cudaGetSymbolAddress((void**)&y,    g_y);
    cudaGetSymbolAddress((void**)&lny,  g_lny);
    cudaGetSymbolAddress((void**)&wqT,  g_wqT);
    cudaGetSymbolAddress((void**)&wkT,  g_wkT);
    cudaGetSymbolAddress((void**)&wvT,  g_wvT);
    cudaGetSymbolAddress((void**)&woT,  g_woT);
    cudaGetSymbolAddress((void**)&w1T,  g_w1T);
    cudaGetSymbolAddress((void**)&w2T,  g_w2T);
    cudaGetSymbolAddress((void**)&w3T,  g_w3T);

    cudaFuncSetAttribute(gemm_f16_kernel<EPI_BIAS,      true >, cudaFuncAttributeMaxDynamicSharedMemorySize, GEMM_SMEM);
    cudaFuncSetAttribute(gemm_f16_kernel<EPI_BIAS_RES,  false>, cudaFuncAttributeMaxDynamicSharedMemorySize, GEMM_SMEM);
    cudaFuncSetAttribute(gemm_f16_kernel<EPI_BIAS_GELU, true >, cudaFuncAttributeMaxDynamicSharedMemorySize, GEMM_SMEM);
    cudaFuncSetAttribute(gemm_f16_kernel<EPI_BIAS_RES2, false>, cudaFuncAttributeMaxDynamicSharedMemorySize, GEMM_SMEM);
    cudaFuncSetAttribute(flash_attn_kernel, cudaFuncAttributeMaxDynamicSharedMemorySize, FA_SMEM);

    // #0-2: transpose wq/wk/wv
    transpose_conv_kernel<<<dim3(32, 32),  dim3(32, 8)>>>(wq, wqT, DD, DD);
    transpose_conv_kernel<<<dim3(32, 32),  dim3(32, 8)>>>(wk, wkT, DD, DD);
    transpose_conv_kernel<<<dim3(32, 32),  dim3(32, 8)>>>(wv, wvT, DD, DD);
    // #3: nx = (half)LN(x)
    ln_kernel<false><<<TOK, 256>>>(x, g1, be1, nx, nullptr);
    // #4: transpose wo
    transpose_conv_kernel<<<dim3(32, 32),  dim3(32, 8)>>>(wo, woT, DD, DD);
    // #5-7: Q/K/V = (half)(nx @ w + b)   <- #5 is the ncu capture slot
    gemm_f16_kernel<EPI_BIAS, true><<<dim3(8, 32), 256, GEMM_SMEM>>>(
        nx, DD, wqT, DD, q, DD, TOK, DD, DD, bq, nullptr, nullptr);
    gemm_f16_kernel<EPI_BIAS, true><<<dim3(8, 32), 256, GEMM_SMEM>>>(
        nx, DD, wkT, DD, k, DD, TOK, DD, DD, bk, nullptr, nullptr);
    gemm_f16_kernel<EPI_BIAS, true><<<dim3(8, 32), 256, GEMM_SMEM>>>(
        nx, DD, wvT, DD, v, DD, TOK, DD, DD, bv, nullptr, nullptr);
    // #8: fused attention -> ctx (fp16)
    flash_attn_kernel<<<dim3(8, BB * HH_), 256, FA_SMEM>>>(q, k, v, relt, ctx);
    // #9: transpose w1
    transpose_conv_kernel<<<dim3(128, 32), dim3(32, 8)>>>(w1, w1T, DD, DFF_);
    // #10: x1 = x + ctx @ wo + bo
    gemm_f16_kernel<EPI_BIAS_RES, false><<<dim3(8, 32), 256, GEMM_SMEM>>>(
        ctx, DD, woT, DD, x1, DD, TOK, DD, DD, bo, x, nullptr);
    // #11: nx2 = LN(x1) (half + exact)
    ln_kernel<true><<<TOK, 256>>>(x1, g2, be2, nx2r, nx2e);
    // #12: ff = (half)gelu(nx2 @ w1 + b1)
    gemm_f16_kernel<EPI_BIAS_GELU, true><<<dim3(32, 32), 256, GEMM_SMEM>>>(
        nx2r, DD, w1T, DD, ff, DFF_, TOK, DFF_, DD, b1, nullptr, nullptr);
    // #13: transpose w2
    transpose_conv_kernel<<<dim3(32, 128), dim3(32, 8)>>>(w2, w2T, DFF_, DD);
    // #14: y = nx2 + ff @ w2 + b2
    gemm_f16_kernel<EPI_BIAS_RES, false><<<dim3(8, 32), 256, GEMM_SMEM>>>(
        ff, DFF_, w2T, DFF_, y, DD, TOK, DD, DFF_, b2, nx2e, nullptr);
    // #15: lny = (half)LN(y)
    ln_kernel<false><<<TOK, 256>>>(y, gf, bf, lny, nullptr);
    // #16: transpose w3
    transpose_conv_kernel<<<dim3(32, 32),  dim3(32, 8)>>>(w3, w3T, DD, DD);
    // #17: out = x1 + y + lny @ w3 + b3
    gemm_f16_kernel<EPI_BIAS_RES2, false><<<dim3(8, 32), 256, GEMM_SMEM>>>(
        lny, DD, w3T, DD, out, DD, TOK, DD, DD, b3, y, x1);
}